// round 1
// baseline (speedup 1.0000x reference)
#include <cuda_runtime.h>
#include <cstdint>

#define R  5
#define NU 4096
#define NV 4096
#define DD 256
#define HH 64
#define BB 4096

// ---------------- scratch (no allocations allowed) ----------------
__device__ float g_cinv[R * NU];     // rowsum (sum over m) -> rsqrt -> c_inv
__device__ float g_rinv[R * NV];     // colsum (sum over n) -> rsqrt -> r_inv
__device__ float g_cwu[R * DD * HH]; // cumsum u_weight
__device__ float g_cwv[R * DD * HH]; // cumsum v_weight
__device__ float g_tu2[R * NU * HH]; // c_inv * (u_feat @ cwu)
__device__ float g_tv2[R * NV * HH]; // r_inv * (v_feat @ cwv)
__device__ float g_yu[NU * HH];      // y_u[n][h]
__device__ float g_yvT[HH * NV];     // y_v transposed [h][m]

// ---------------- tf32 mma helper ----------------
__device__ __forceinline__ void mma_tf32(float* d, const uint32_t* a, const uint32_t* b) {
    asm volatile(
        "mma.sync.aligned.m16n8k8.row.col.f32.tf32.tf32.f32 "
        "{%0,%1,%2,%3},{%4,%5,%6,%7},{%8,%9},{%0,%1,%2,%3};"
        : "+f"(d[0]), "+f"(d[1]), "+f"(d[2]), "+f"(d[3])
        : "r"(a[0]), "r"(a[1]), "r"(a[2]), "r"(a[3]),
          "r"(b[0]), "r"(b[1]));
}

// ---------------- K0: zero accumulators ----------------
__global__ void zero_kernel() {
    int i = blockIdx.x * 256 + threadIdx.x;   // grid covers 262144
    if (i < R * NU) g_cinv[i] = 0.f;
    if (i < R * NV) g_rinv[i] = 0.f;
    if (i < NU * HH) g_yu[i] = 0.f;
    if (i < HH * NV) g_yvT[i] = 0.f;
}

// ---------------- K1: row & col sums of support ----------------
// grid (64 rowblocks, R), 256 threads. CTA covers 64 rows x 4096 cols.
__global__ __launch_bounds__(256) void sums_kernel(const float* __restrict__ support) {
    int r = blockIdx.y;
    int nb = blockIdx.x;
    int t = threadIdx.x;
    int warp = t >> 5, lane = t & 31;
    const float* base = support + (size_t)r * NU * NV + (size_t)nb * 64 * NV;

    float colacc[16];
#pragma unroll
    for (int i = 0; i < 16; ++i) colacc[i] = 0.f;

    __shared__ float rowpart[64 * 8];

    for (int row = 0; row < 64; ++row) {
        const float4* p = (const float4*)(base + (size_t)row * NV);
        float rs = 0.f;
#pragma unroll
        for (int j = 0; j < 4; ++j) {
            float4 v = p[t + j * 256];
            colacc[j * 4 + 0] += v.x;
            colacc[j * 4 + 1] += v.y;
            colacc[j * 4 + 2] += v.z;
            colacc[j * 4 + 3] += v.w;
            rs += (v.x + v.y) + (v.z + v.w);
        }
#pragma unroll
        for (int o = 16; o; o >>= 1) rs += __shfl_xor_sync(0xffffffffu, rs, o);
        if (lane == 0) rowpart[row * 8 + warp] = rs;
    }
    __syncthreads();
    if (t < 64) {
        float s = 0.f;
#pragma unroll
        for (int w = 0; w < 8; ++w) s += rowpart[t * 8 + w];
        g_cinv[r * NU + nb * 64 + t] = s;   // raw rowsum for now
    }
#pragma unroll
    for (int j = 0; j < 4; ++j)
#pragma unroll
        for (int c = 0; c < 4; ++c)
            atomicAdd(&g_rinv[r * NV + 4 * t + 1024 * j + c], colacc[j * 4 + c]);
}

// ---------------- K2: turn sums into inverse-sqrt scalings ----------------
__global__ void inv_kernel() {
    int i = blockIdx.x * 256 + threadIdx.x;
    if (i < R * NU) {
        float v = g_cinv[i];
        g_cinv[i] = (v > 0.f) ? rsqrtf(v) : 0.f;
    }
    if (i < R * NV) {
        float v = g_rinv[i];
        g_rinv[i] = (v > 0.f) ? rsqrtf(v) : 0.f;
    }
}

// ---------------- K3: cumsum of weights over r ----------------
__global__ void cumsum_kernel(const float* __restrict__ uw, const float* __restrict__ vw) {
    int i = blockIdx.x * 256 + threadIdx.x;   // < DD*HH
    int which = blockIdx.y;
    const float* w = which ? vw : uw;
    float* cw = which ? g_cwv : g_cwu;
    float a = 0.f;
#pragma unroll
    for (int r = 0; r < R; ++r) {
        a += w[r * DD * HH + i];
        cw[r * DD * HH + i] = a;
    }
}

// ---------------- K4: tmp GEMMs, scaled by inv ----------------
// grid (32 nblocks, R, 2 which), 256 threads. Tile [128 x 64], K=256.
__global__ __launch_bounds__(256) void tmp_kernel(const float* __restrict__ u_feat,
                                                  const float* __restrict__ v_feat) {
    __shared__ float sA[128 * 36];
    __shared__ float sB[32 * 68];
    int which = blockIdx.z;
    int r = blockIdx.y;
    int n0 = blockIdx.x * 128;
    const float* feat = which ? v_feat : u_feat;
    const float* cw = which ? g_cwv : g_cwu;
    const float* inv = which ? g_rinv : g_cinv;
    float* out = which ? g_tv2 : g_tu2;

    int t = threadIdx.x;
    int tx = t & 15, ty = t >> 4;

    float acc[8][4];
#pragma unroll
    for (int j = 0; j < 8; ++j)
#pragma unroll
        for (int c = 0; c < 4; ++c) acc[j][c] = 0.f;

    for (int kc = 0; kc < DD / 32; ++kc) {
        int k0 = kc * 32;
#pragma unroll
        for (int i = 0; i < 4; ++i) {
            int q = t + 256 * i;
            int row = q >> 3, c4 = q & 7;
            float4 v = *(const float4*)(feat + (size_t)(n0 + row) * DD + k0 + c4 * 4);
            *(float4*)&sA[row * 36 + c4 * 4] = v;
        }
#pragma unroll
        for (int i = 0; i < 2; ++i) {
            int q = t + 256 * i;
            int row = q >> 4, c4 = q & 15;
            float4 v = *(const float4*)(cw + (size_t)r * DD * HH + (size_t)(k0 + row) * HH + c4 * 4);
            *(float4*)&sB[row * 68 + c4 * 4] = v;
        }
        __syncthreads();
#pragma unroll 4
        for (int kk = 0; kk < 32; ++kk) {
            float4 bv = *(float4*)&sB[kk * 68 + tx * 4];
#pragma unroll
            for (int j = 0; j < 8; ++j) {
                float a = sA[(ty * 8 + j) * 36 + kk];
                acc[j][0] = fmaf(a, bv.x, acc[j][0]);
                acc[j][1] = fmaf(a, bv.y, acc[j][1]);
                acc[j][2] = fmaf(a, bv.z, acc[j][2]);
                acc[j][3] = fmaf(a, bv.w, acc[j][3]);
            }
        }
        __syncthreads();
    }
#pragma unroll
    for (int j = 0; j < 8; ++j) {
        int n = n0 + ty * 8 + j;
        float iv = inv[r * NU + n];
#pragma unroll
        for (int c = 0; c < 4; ++c)
            out[((size_t)r * NU + n) * HH + tx * 4 + c] = iv * acc[j][c];
    }
}

// ---------------- K5: y_u = c_inv * sum_{r,m} support[r,n,m] * tv2[r,m,h] ----------------
// grid (32 ntiles, R, 2 msplit), 256 threads = 8 warps. Tile D[128n x 64h].
__global__ __launch_bounds__(256) void yu_kernel(const float* __restrict__ support) {
    __shared__ float sA[128 * 36];  // support tile [n][k=m]
    __shared__ float sB[32 * 68];   // tv2 tile    [k=m][h]
    int r = blockIdx.y;
    int n0 = blockIdx.x * 128;
    int mbase = blockIdx.z * (NV / 2);
    int t = threadIdx.x, lane = t & 31, warp = t >> 5;
    int g = lane >> 2, tg = lane & 3;
    int wy = warp >> 1, wx = warp & 1;

    float acc[2][4][4];
#pragma unroll
    for (int a = 0; a < 2; ++a)
#pragma unroll
        for (int b = 0; b < 4; ++b)
#pragma unroll
            for (int c = 0; c < 4; ++c) acc[a][b][c] = 0.f;

    const float* supR = support + (size_t)r * NU * NV;

    for (int kc = 0; kc < (NV / 2) / 32; ++kc) {
        int k0 = mbase + kc * 32;
#pragma unroll
        for (int i = 0; i < 4; ++i) {
            int q = t + 256 * i;
            int row = q >> 3, c4 = q & 7;
            float4 v = *(const float4*)(supR + (size_t)(n0 + row) * NV + k0 + c4 * 4);
            *(float4*)&sA[row * 36 + c4 * 4] = v;
        }
#pragma unroll
        for (int i = 0; i < 2; ++i) {
            int q = t + 256 * i;
            int row = q >> 4, c4 = q & 15;
            float4 v = *(const float4*)(g_tv2 + ((size_t)r * NV + k0 + row) * HH + c4 * 4);
            *(float4*)&sB[row * 68 + c4 * 4] = v;
        }
        __syncthreads();
#pragma unroll
        for (int ks = 0; ks < 4; ++ks) {
            uint32_t a[2][4], b[4][2];
#pragma unroll
            for (int rt = 0; rt < 2; ++rt) {
                int rb = wy * 32 + rt * 16;
                a[rt][0] = __float_as_uint(sA[(rb + g) * 36 + ks * 8 + tg]);
                a[rt][1] = __float_as_uint(sA[(rb + g + 8) * 36 + ks * 8 + tg]);
                a[rt][2] = __float_as_uint(sA[(rb + g) * 36 + ks * 8 + tg + 4]);
                a[rt][3] = __float_as_uint(sA[(rb + g + 8) * 36 + ks * 8 + tg + 4]);
            }
#pragma unroll
            for (int ct = 0; ct < 4; ++ct) {
                int cb = wx * 32 + ct * 8;
                b[ct][0] = __float_as_uint(sB[(ks * 8 + tg) * 68 + cb + g]);
                b[ct][1] = __float_as_uint(sB[(ks * 8 + tg + 4) * 68 + cb + g]);
            }
#pragma unroll
            for (int rt = 0; rt < 2; ++rt)
#pragma unroll
                for (int ct = 0; ct < 4; ++ct) mma_tf32(acc[rt][ct], a[rt], b[ct]);
        }
        __syncthreads();
    }
    // epilogue: scale by c_inv[r,n], atomically accumulate over (r, msplit)
#pragma unroll
    for (int rt = 0; rt < 2; ++rt) {
        int n1 = n0 + wy * 32 + rt * 16 + g;
        int n2 = n1 + 8;
        float c1 = g_cinv[r * NU + n1];
        float c2 = g_cinv[r * NU + n2];
#pragma unroll
        for (int ct = 0; ct < 4; ++ct) {
            int h = wx * 32 + ct * 8 + tg * 2;
            atomicAdd(&g_yu[n1 * HH + h], c1 * acc[rt][ct][0]);
            atomicAdd(&g_yu[n1 * HH + h + 1], c1 * acc[rt][ct][1]);
            atomicAdd(&g_yu[n2 * HH + h], c2 * acc[rt][ct][2]);
            atomicAdd(&g_yu[n2 * HH + h + 1], c2 * acc[rt][ct][3]);
        }
    }
}

// ---------------- K6: y_v = r_inv * sum_{r,n} support[r,n,m] * tu2[r,n,h] ----------------
// Computed as D[64h x 128m] with A = tu2^T, B = support. grid (32 mtiles, R, 2 nsplit).
__global__ __launch_bounds__(256) void yv_kernel(const float* __restrict__ support) {
    __shared__ float sB[32 * 132];  // support tile [k=n][m]
    __shared__ float sA[32 * 68];   // tu2 tile     [k=n][h]
    int r = blockIdx.y;
    int m0 = blockIdx.x * 128;
    int nbase = blockIdx.z * (NU / 2);
    int t = threadIdx.x, lane = t & 31, warp = t >> 5;
    int g = lane >> 2, tg = lane & 3;
    int wy = warp >> 2, wx = warp & 3;

    float acc[2][4][4];
#pragma unroll
    for (int a = 0; a < 2; ++a)
#pragma unroll
        for (int b = 0; b < 4; ++b)
#pragma unroll
            for (int c = 0; c < 4; ++c) acc[a][b][c] = 0.f;

    const float* supR = support + (size_t)r * NU * NV;

    for (int kc = 0; kc < (NU / 2) / 32; ++kc) {
        int k0 = nbase + kc * 32;
#pragma unroll
        for (int i = 0; i < 4; ++i) {
            int q = t + 256 * i;
            int row = q >> 5, c4 = q & 31;
            float4 v = *(const float4*)(supR + (size_t)(k0 + row) * NV + m0 + c4 * 4);
            *(float4*)&sB[row * 132 + c4 * 4] = v;
        }
#pragma unroll
        for (int i = 0; i < 2; ++i) {
            int q = t + 256 * i;
            int row = q >> 4, c4 = q & 15;
            float4 v = *(const float4*)(g_tu2 + ((size_t)r * NU + k0 + row) * HH + c4 * 4);
            *(float4*)&sA[row * 68 + c4 * 4] = v;
        }
        __syncthreads();
#pragma unroll
        for (int ks = 0; ks < 4; ++ks) {
            uint32_t a[2][4], b[4][2];
#pragma unroll
            for (int rt = 0; rt < 2; ++rt) {
                int hb = wy * 32 + rt * 16;
                a[rt][0] = __float_as_uint(sA[(ks * 8 + tg) * 68 + hb + g]);
                a[rt][1] = __float_as_uint(sA[(ks * 8 + tg) * 68 + hb + g + 8]);
                a[rt][2] = __float_as_uint(sA[(ks * 8 + tg + 4) * 68 + hb + g]);
                a[rt][3] = __float_as_uint(sA[(ks * 8 + tg + 4) * 68 + hb + g + 8]);
            }
#pragma unroll
            for (int ct = 0; ct < 4; ++ct) {
                int mb = wx * 32 + ct * 8;
                b[ct][0] = __float_as_uint(sB[(ks * 8 + tg) * 132 + mb + g]);
                b[ct][1] = __float_as_uint(sB[(ks * 8 + tg + 4) * 132 + mb + g]);
            }
#pragma unroll
            for (int rt = 0; rt < 2; ++rt)
#pragma unroll
                for (int ct = 0; ct < 4; ++ct) mma_tf32(acc[rt][ct], a[rt], b[ct]);
        }
        __syncthreads();
    }
    // epilogue: scale by r_inv[r,m], accumulate into transposed y_v
#pragma unroll
    for (int rt = 0; rt < 2; ++rt) {
        int h1 = wy * 32 + rt * 16 + g;
        int h2 = h1 + 8;
#pragma unroll
        for (int ct = 0; ct < 4; ++ct) {
            int m = m0 + wx * 32 + ct * 8 + tg * 2;
            float ri0 = g_rinv[r * NV + m];
            float ri1 = g_rinv[r * NV + m + 1];
            atomicAdd(&g_yvT[h1 * NV + m], ri0 * acc[rt][ct][0]);
            atomicAdd(&g_yvT[h1 * NV + m + 1], ri1 * acc[rt][ct][1]);
            atomicAdd(&g_yvT[h2 * NV + m], ri0 * acc[rt][ct][2]);
            atomicAdd(&g_yvT[h2 * NV + m + 1], ri1 * acc[rt][ct][3]);
        }
    }
}

// ---------------- K7: gather + bias + relu ----------------
__global__ void gather_kernel(const int* __restrict__ u, const int* __restrict__ v,
                              const float* __restrict__ bias, float* __restrict__ out) {
    int idx = blockIdx.x * 256 + threadIdx.x;  // < BB*HH
    int b = idx >> 6, h = idx & 63;
    float bi = bias[h];
    float zu = g_yu[u[b] * HH + h] + bi;
    float zv = g_yvT[h * NV + v[b]] + bi;
    out[idx] = fmaxf(zu, 0.f);
    out[BB * HH + idx] = fmaxf(zv, 0.f);
}

// ---------------- launcher ----------------
extern "C" void kernel_launch(void* const* d_in, const int* in_sizes, int n_in,
                              void* d_out, int out_size) {
    const float* u_feat = (const float*)d_in[0];
    const float* v_feat = (const float*)d_in[1];
    const int* u = (const int*)d_in[2];
    const int* v = (const int*)d_in[3];
    const float* support = (const float*)d_in[4];
    const float* u_weight = (const float*)d_in[5];
    const float* v_weight = (const float*)d_in[6];
    const float* u_bias = (const float*)d_in[7];
    float* out = (float*)d_out;

    zero_kernel<<<(NU * HH + 255) / 256, 256>>>();
    sums_kernel<<<dim3(64, R), 256>>>(support);
    inv_kernel<<<(R * NU + 255) / 256, 256>>>();
    cumsum_kernel<<<dim3(DD * HH / 256, 2), 256>>>(u_weight, v_weight);
    tmp_kernel<<<dim3(32, R, 2), 256>>>(u_feat, v_feat);
    yu_kernel<<<dim3(32, R, 2), 256>>>(support);
    yv_kernel<<<dim3(32, R, 2), 256>>>(support);
    gather_kernel<<<BB * HH / 256, 256>>>(u, v, u_bias, out);
}